// round 1
// baseline (speedup 1.0000x reference)
#include <cuda_runtime.h>
#include <float.h>

#define BB 2
#define HH 16
#define SSEQ 2048
#define DD 64
#define ROWS 16            // q rows per block
#define SSTRIDE 2052       // padded score row stride (floats)
#define KTILE 256          // k columns per phase-1 tile
#define SKT_STRIDE 260     // padded transposed-K row stride (floats)
#define VTILE 128          // v rows per phase-3 tile
#define NTHREADS 256

#define INV_T 0.125f       // 1/8.0 temperature
#define NEG_INF_F (-1000000000.0f)

// dynamic smem: sS[16*2052] + sQ[16*64] + sKT[64*260]  (sKT region reused for sV[128*64])
#define SMEM_FLOATS (ROWS * SSTRIDE + ROWS * DD + 64 * SKT_STRIDE)
#define SMEM_BYTES (SMEM_FLOATS * 4)

__global__ void __launch_bounds__(NTHREADS, 1)
sdpa_kernel(const float* __restrict__ q, const float* __restrict__ k,
            const float* __restrict__ v, const int* __restrict__ mask,
            float* __restrict__ out, float* __restrict__ attn)
{
    extern __shared__ float smem[];
    float* sS  = smem;                     // ROWS * SSTRIDE
    float* sQ  = sS + ROWS * SSTRIDE;      // ROWS * DD
    float* sKT = sQ + ROWS * DD;           // 64 * SKT_STRIDE (reused as sV)

    const int t  = threadIdx.x;
    const int h  = blockIdx.y;
    const int b  = blockIdx.z;
    const int q0 = blockIdx.x * ROWS;

    const int bh = b * HH + h;
    const float* qg = q + ((long)bh * SSEQ + q0) * DD;
    const float* kg = k + (long)bh * SSEQ * DD;
    const float* vg = v + (long)bh * SSEQ * DD;
    const int*   mg = mask + ((long)b * SSEQ + q0) * SSEQ;
    float* attng = attn + ((long)bh * SSEQ + q0) * SSEQ;
    float* outg  = out  + ((long)bh * SSEQ + q0) * DD;

    // ---- load Q tile (16x64) ----
    #pragma unroll
    for (int i = 0; i < (ROWS * DD) / NTHREADS; ++i) {
        int idx = t + i * NTHREADS;
        sQ[idx] = qg[idx];
    }

    // ================= Phase 1: S = (Q K^T) * invT, masked, into sS =================
    const int tx = t & 63;   // col group (4 cols each)
    const int ty = t >> 6;   // row group (4 rows each)

    for (int kt = 0; kt < SSEQ; kt += KTILE) {
        __syncthreads();
        // load K tile transposed: sKT[d][jloc], jloc in [0,256)
        #pragma unroll 8
        for (int i = 0; i < (KTILE * DD) / NTHREADS; ++i) {
            int idx  = t + i * NTHREADS;
            int jloc = idx >> 6;
            int d    = idx & 63;
            sKT[d * SKT_STRIDE + jloc] = kg[(kt + jloc) * DD + d];
        }
        __syncthreads();

        float acc[4][4];
        #pragma unroll
        for (int rr = 0; rr < 4; ++rr)
            #pragma unroll
            for (int jj = 0; jj < 4; ++jj) acc[rr][jj] = 0.0f;

        #pragma unroll 8
        for (int d = 0; d < DD; ++d) {
            float4 kv = *(const float4*)&sKT[d * SKT_STRIDE + tx * 4];
            #pragma unroll
            for (int rr = 0; rr < 4; ++rr) {
                float qv = sQ[(ty * 4 + rr) * DD + d];
                acc[rr][0] += qv * kv.x;
                acc[rr][1] += qv * kv.y;
                acc[rr][2] += qv * kv.z;
                acc[rr][3] += qv * kv.w;
            }
        }

        // scale + mask + store to score strip
        #pragma unroll
        for (int rr = 0; rr < 4; ++rr) {
            int r  = ty * 4 + rr;
            int jb = kt + tx * 4;
            int4 m4 = *(const int4*)&mg[r * SSEQ + jb];
            float* srow = &sS[r * SSTRIDE + jb];
            srow[0] = m4.x ? acc[rr][0] * INV_T : NEG_INF_F;
            srow[1] = m4.y ? acc[rr][1] * INV_T : NEG_INF_F;
            srow[2] = m4.z ? acc[rr][2] * INV_T : NEG_INF_F;
            srow[3] = m4.w ? acc[rr][3] * INV_T : NEG_INF_F;
        }
    }
    __syncthreads();

    // ================= Phase 2: softmax per row + write attn =================
    {
        const int warp = t >> 5;
        const int lane = t & 31;
        #pragma unroll
        for (int rw = 0; rw < 2; ++rw) {
            int r = warp * 2 + rw;
            float4* srow4 = (float4*)&sS[r * SSTRIDE];
            float4* arow4 = (float4*)&attng[(long)r * SSEQ];

            float m = -FLT_MAX;
            #pragma unroll 4
            for (int j4 = lane; j4 < SSEQ / 4; j4 += 32) {
                float4 x = srow4[j4];
                m = fmaxf(m, fmaxf(fmaxf(x.x, x.y), fmaxf(x.z, x.w)));
            }
            #pragma unroll
            for (int o = 16; o; o >>= 1) m = fmaxf(m, __shfl_xor_sync(0xffffffffu, m, o));

            float sum = 0.0f;
            #pragma unroll 4
            for (int j4 = lane; j4 < SSEQ / 4; j4 += 32) {
                float4 x = srow4[j4];
                x.x = __expf(x.x - m);
                x.y = __expf(x.y - m);
                x.z = __expf(x.z - m);
                x.w = __expf(x.w - m);
                sum += (x.x + x.y) + (x.z + x.w);
                srow4[j4] = x;
            }
            #pragma unroll
            for (int o = 16; o; o >>= 1) sum += __shfl_xor_sync(0xffffffffu, sum, o);
            float inv = 1.0f / sum;

            #pragma unroll 4
            for (int j4 = lane; j4 < SSEQ / 4; j4 += 32) {
                float4 x = srow4[j4];
                x.x *= inv; x.y *= inv; x.z *= inv; x.w *= inv;
                srow4[j4] = x;     // keep normalized probs for phase 3
                arow4[j4] = x;     // write attn output
            }
        }
    }
    __syncthreads();

    // ================= Phase 3: out = P @ V =================
    // 256 threads = 4 j-partitions x (4 row-groups x 16 d-groups)
    const int pj  = t >> 6;        // j partition 0..3
    const int t64 = t & 63;
    const int txd = t64 & 15;      // d group (4 cols)
    const int tyr = t64 >> 4;      // row group (4 rows)

    float vacc[4][4];
    #pragma unroll
    for (int rr = 0; rr < 4; ++rr)
        #pragma unroll
        for (int dd = 0; dd < 4; ++dd) vacc[rr][dd] = 0.0f;

    float* sV = sKT;               // reuse region: VTILE * DD floats
    for (int vt = 0; vt < SSEQ; vt += VTILE) {
        __syncthreads();
        #pragma unroll 8
        for (int i = 0; i < (VTILE * DD) / NTHREADS; ++i) {
            int idx = t + i * NTHREADS;
            sV[idx] = vg[vt * DD + idx];
        }
        __syncthreads();

        #pragma unroll 8
        for (int ji = 0; ji < VTILE / 4; ++ji) {
            int jloc = pj * (VTILE / 4) + ji;
            float4 vv = *(const float4*)&sV[jloc * DD + txd * 4];
            #pragma unroll
            for (int rr = 0; rr < 4; ++rr) {
                float p = sS[(tyr * 4 + rr) * SSTRIDE + vt + jloc];
                vacc[rr][0] += p * vv.x;
                vacc[rr][1] += p * vv.y;
                vacc[rr][2] += p * vv.z;
                vacc[rr][3] += p * vv.w;
            }
        }
    }
    __syncthreads();

    // reduce the 4 j-partitions via smem scratch (sS is dead now)
    float* scratch = sS;           // 4 * 1024 floats
    #pragma unroll
    for (int rr = 0; rr < 4; ++rr)
        #pragma unroll
        for (int dd = 0; dd < 4; ++dd)
            scratch[pj * (ROWS * DD) + (tyr * 4 + rr) * DD + txd * 4 + dd] = vacc[rr][dd];
    __syncthreads();

    #pragma unroll
    for (int i = 0; i < (ROWS * DD) / NTHREADS; ++i) {
        int o = t + i * NTHREADS;
        float s = scratch[o] + scratch[ROWS * DD + o]
                + scratch[2 * ROWS * DD + o] + scratch[3 * ROWS * DD + o];
        outg[o] = s;
    }
}

extern "C" void kernel_launch(void* const* d_in, const int* in_sizes, int n_in,
                              void* d_out, int out_size)
{
    const float* q    = (const float*)d_in[0];
    const float* k    = (const float*)d_in[1];
    const float* v    = (const float*)d_in[2];
    const int*   mask = (const int*)d_in[3];

    float* out  = (float*)d_out;
    float* attn = out + (size_t)BB * HH * SSEQ * DD;   // tuple order: (output, attn)

    cudaFuncSetAttribute(sdpa_kernel, cudaFuncAttributeMaxDynamicSharedMemorySize, SMEM_BYTES);

    dim3 grid(SSEQ / ROWS, HH, BB);
    sdpa_kernel<<<grid, NTHREADS, SMEM_BYTES>>>(q, k, v, mask, out, attn);
}

// round 3
// speedup vs baseline: 2.5992x; 2.5992x over previous
#include <cuda_runtime.h>
#include <stdint.h>

#define SQ 2048
#define DH 64
#define NH 16
#define NB 2
#define INV_T 0.125f

// row-sum scratch: [B*H][S]
__device__ float g_rowsum[NB * NH * SQ];

// ---------------- helpers ----------------

__device__ __forceinline__ void split_tf32(float x, uint32_t& hi, uint32_t& lo) {
    uint32_t h;
    asm("cvt.rna.tf32.f32 %0, %1;" : "=r"(h) : "f"(x));
    float r = x - __uint_as_float(h);
    uint32_t l;
    asm("cvt.rna.tf32.f32 %0, %1;" : "=r"(l) : "f"(r));
    hi = h; lo = l;
}

__device__ __forceinline__ void mma_tf32(float* c, const uint32_t* a, const uint32_t* b) {
    asm volatile(
        "mma.sync.aligned.m16n8k8.row.col.f32.tf32.tf32.f32 "
        "{%0,%1,%2,%3}, {%4,%5,%6,%7}, {%8,%9}, {%0,%1,%2,%3};"
        : "+f"(c[0]), "+f"(c[1]), "+f"(c[2]), "+f"(c[3])
        : "r"(a[0]), "r"(a[1]), "r"(a[2]), "r"(a[3]), "r"(b[0]), "r"(b[1]));
}

// ================= Kernel 1: p' = exp(mask(QK^T/T)), row sums =================
// CTA: 64 q-rows, 256 threads (8 warps: 4 in M x 2 in N), j-tiles of 128.
#define K1_SMEM_FLOATS (64 * 68 + 128 * 68 + 64)

__global__ void __launch_bounds__(256)
k1_qk(const float* __restrict__ q, const float* __restrict__ k,
      const int* __restrict__ mask, float* __restrict__ attn)
{
    extern __shared__ float sm[];
    float* sQ   = sm;              // 64 x stride 68
    float* sK   = sm + 64 * 68;    // 128 x stride 68
    float* sSum = sK + 128 * 68;   // 64

    const int t  = threadIdx.x;
    const int h  = blockIdx.y;
    const int b  = blockIdx.z;
    const int q0 = blockIdx.x * 64;
    const int bh = b * NH + h;

    const float* qg = q + ((size_t)bh * SQ + q0) * DH;
    const float* kg = k + (size_t)bh * SQ * DH;
    const int*   mg = mask + ((size_t)b * SQ + q0) * SQ;
    float*       ag = attn + ((size_t)bh * SQ + q0) * SQ;

    // load Q tile 64x64 (coalesced), stride 68
    #pragma unroll
    for (int i = 0; i < 4; ++i) {
        int idx = t + i * 256;
        int r = idx >> 4, dg = idx & 15;
        *(float4*)&sQ[r * 68 + dg * 4] = *(const float4*)&qg[r * DH + dg * 4];
    }
    if (t < 64) sSum[t] = 0.0f;

    const int lane = t & 31, warp = t >> 5;
    const int wm = warp >> 1;     // 0..3 : rows wm*16
    const int wn = warp & 1;      // 0..1 : j-offset wn*64
    const int g  = lane >> 2;     // 0..7
    const int tg = lane & 3;      // 0..3

    float rs0 = 0.0f, rs1 = 0.0f;
    const int rl0 = wm * 16 + g, rl1 = rl0 + 8;

    for (int jt = 0; jt < 16; ++jt) {
        __syncthreads();
        // load K tile 128x64 (coalesced)
        #pragma unroll
        for (int i = 0; i < 8; ++i) {
            int idx = t + i * 256;
            int jl = idx >> 4, dg = idx & 15;
            *(float4*)&sK[jl * 68 + dg * 4] =
                *(const float4*)&kg[(jt * 128 + jl) * DH + dg * 4];
        }
        __syncthreads();

        float acc[8][4];
        #pragma unroll
        for (int nt = 0; nt < 8; ++nt)
            acc[nt][0] = acc[nt][1] = acc[nt][2] = acc[nt][3] = 0.0f;

        #pragma unroll
        for (int kc = 0; kc < 8; ++kc) {
            // A-frag (Q rows): a0:(g,tg) a1:(g+8,tg) a2:(g,tg+4) a3:(g+8,tg+4)
            const float* qa = &sQ[rl0 * 68 + kc * 8 + tg];
            uint32_t ah[4], al[4];
            split_tf32(qa[0],          ah[0], al[0]);
            split_tf32(qa[8 * 68],     ah[1], al[1]);
            split_tf32(qa[4],          ah[2], al[2]);
            split_tf32(qa[8 * 68 + 4], ah[3], al[3]);
            #pragma unroll
            for (int nt = 0; nt < 8; ++nt) {
                // B col-major (k x n): B(k,n) = K[j = n][d = k]
                int nl = wn * 64 + nt * 8 + g;
                float b0 = sK[nl * 68 + kc * 8 + tg];
                float b1 = sK[nl * 68 + kc * 8 + tg + 4];
                uint32_t bh2[2], bl2[2];
                split_tf32(b0, bh2[0], bl2[0]);
                split_tf32(b1, bh2[1], bl2[1]);
                mma_tf32(acc[nt], ah, bh2);
                mma_tf32(acc[nt], ah, bl2);
                mma_tf32(acc[nt], al, bh2);
            }
        }

        // epilogue: mask, scale, exp, store p', accumulate row sums
        #pragma unroll
        for (int nt = 0; nt < 8; ++nt) {
            int jc = jt * 128 + wn * 64 + nt * 8 + tg * 2;
            int2 m0 = *(const int2*)&mg[rl0 * SQ + jc];
            int2 m1 = *(const int2*)&mg[rl1 * SQ + jc];
            float e00 = m0.x ? __expf(acc[nt][0] * INV_T) : 0.0f;
            float e01 = m0.y ? __expf(acc[nt][1] * INV_T) : 0.0f;
            float e10 = m1.x ? __expf(acc[nt][2] * INV_T) : 0.0f;
            float e11 = m1.y ? __expf(acc[nt][3] * INV_T) : 0.0f;
            *(float2*)&ag[rl0 * SQ + jc] = make_float2(e00, e01);
            *(float2*)&ag[rl1 * SQ + jc] = make_float2(e10, e11);
            rs0 += e00 + e01;
            rs1 += e10 + e11;
        }
    }

    // reduce row sums over the 4-lane tg group, combine the 2 N-warps via smem
    rs0 += __shfl_xor_sync(0xffffffffu, rs0, 1);
    rs0 += __shfl_xor_sync(0xffffffffu, rs0, 2);
    rs1 += __shfl_xor_sync(0xffffffffu, rs1, 1);
    rs1 += __shfl_xor_sync(0xffffffffu, rs1, 2);
    if (tg == 0) {
        atomicAdd(&sSum[rl0], rs0);
        atomicAdd(&sSum[rl1], rs1);
    }
    __syncthreads();
    if (t < 64) g_rowsum[(size_t)bh * SQ + q0 + t] = sSum[t];
}

// ================= Kernel 2: attn = p'/rowsum (in place), out = attn @ V =================
// CTA: 64 q-rows, 256 threads (4 warps in M x 2 warps in N(d)), j-tiles of 64.
#define K2_SMEM_FLOATS (64 * 68 + 64 * 68 + 64)

__global__ void __launch_bounds__(256)
k2_pv(const float* __restrict__ v, float* __restrict__ attn, float* __restrict__ out)
{
    extern __shared__ float sm[];
    float* sP   = sm;             // 64 x stride 68 (normalized probs)
    float* sV   = sm + 64 * 68;   // 64 x stride 68 (V natural [j][d])
    float* sInv = sV + 64 * 68;   // 64

    const int t  = threadIdx.x;
    const int h  = blockIdx.y;
    const int b  = blockIdx.z;
    const int q0 = blockIdx.x * 64;
    const int bh = b * NH + h;

    const float* vg = v + (size_t)bh * SQ * DH;
    float*       ag = attn + ((size_t)bh * SQ + q0) * SQ;
    float*       og = out  + ((size_t)bh * SQ + q0) * DH;

    if (t < 64) sInv[t] = 1.0f / g_rowsum[(size_t)bh * SQ + q0 + t];

    const int lane = t & 31, warp = t >> 5;
    const int wm = warp >> 1;   // rows wm*16
    const int wn = warp & 1;    // d-offset wn*32
    const int g  = lane >> 2;
    const int tg = lane & 3;
    const int rl0 = wm * 16 + g, rl1 = rl0 + 8;

    float acc[4][4];
    #pragma unroll
    for (int nt = 0; nt < 4; ++nt)
        acc[nt][0] = acc[nt][1] = acc[nt][2] = acc[nt][3] = 0.0f;

    for (int jt = 0; jt < 32; ++jt) {
        __syncthreads();
        // load p' tile 64x64, normalize, write final attn in place, stage in sP
        #pragma unroll
        for (int i = 0; i < 4; ++i) {
            int idx = t + i * 256;
            int r = idx >> 4, jg = idx & 15;
            float4 x = *(float4*)&ag[r * SQ + jt * 64 + jg * 4];
            float iv = sInv[r];
            x.x *= iv; x.y *= iv; x.z *= iv; x.w *= iv;
            *(float4*)&ag[r * SQ + jt * 64 + jg * 4] = x;
            *(float4*)&sP[r * 68 + jg * 4] = x;
        }
        // load V tile 64x64 natural layout
        #pragma unroll
        for (int i = 0; i < 4; ++i) {
            int idx = t + i * 256;
            int jl = idx >> 4, dg = idx & 15;
            *(float4*)&sV[jl * 68 + dg * 4] =
                *(const float4*)&vg[(jt * 64 + jl) * DH + dg * 4];
        }
        __syncthreads();

        #pragma unroll
        for (int kc = 0; kc < 8; ++kc) {
            // A-frag from P rows
            const float* pa = &sP[rl0 * 68 + kc * 8 + tg];
            uint32_t ah[4], al[4];
            split_tf32(pa[0],          ah[0], al[0]);
            split_tf32(pa[8 * 68],     ah[1], al[1]);
            split_tf32(pa[4],          ah[2], al[2]);
            split_tf32(pa[8 * 68 + 4], ah[3], al[3]);
            #pragma unroll
            for (int nt = 0; nt < 4; ++nt) {
                // B col-major (k x n): B(k,n) = V[j = k][d = n]
                int n = wn * 32 + nt * 8 + g;
                float b0 = sV[(kc * 8 + tg) * 68 + n];
                float b1 = sV[(kc * 8 + tg + 4) * 68 + n];
                uint32_t bh2[2], bl2[2];
                split_tf32(b0, bh2[0], bl2[0]);
                split_tf32(b1, bh2[1], bl2[1]);
                mma_tf32(acc[nt], ah, bh2);
                mma_tf32(acc[nt], ah, bl2);
                mma_tf32(acc[nt], al, bh2);
            }
        }
    }

    // write output (full k-reduction is complete; no cross-warp reduce needed)
    #pragma unroll
    for (int nt = 0; nt < 4; ++nt) {
        int dc = wn * 32 + nt * 8 + tg * 2;
        *(float2*)&og[rl0 * DH + dc] = make_float2(acc[nt][0], acc[nt][1]);
        *(float2*)&og[rl1 * DH + dc] = make_float2(acc[nt][2], acc[nt][3]);
    }
}

// ================= launch =================

extern "C" void kernel_launch(void* const* d_in, const int* in_sizes, int n_in,
                              void* d_out, int out_size)
{
    const float* q    = (const float*)d_in[0];
    const float* k    = (const float*)d_in[1];
    const float* v    = (const float*)d_in[2];
    const int*   mask = (const int*)d_in[3];

    float* out  = (float*)d_out;
    float* attn = out + (size_t)NB * NH * SQ * DH;   // tuple order: (output, attn)

    cudaFuncSetAttribute(k1_qk, cudaFuncAttributeMaxDynamicSharedMemorySize,
                         K1_SMEM_FLOATS * 4);
    cudaFuncSetAttribute(k2_pv, cudaFuncAttributeMaxDynamicSharedMemorySize,
                         K2_SMEM_FLOATS * 4);

    dim3 grid(SQ / 64, NH, NB);
    k1_qk<<<grid, 256, K1_SMEM_FLOATS * 4>>>(q, k, mask, attn);
    k2_pv<<<grid, 256, K2_SMEM_FLOATS * 4>>>(v, attn, out);
}